// round 8
// baseline (speedup 1.0000x reference)
#include <cuda_runtime.h>
#include <math.h>

#define N_NODES 4096
#define KDIM    512
#define D_H     64
#define HEADS   8
#define MAXD    192
#define CH      64
#define KSPLIT  8
#define KS      64                  // K per split
#define BM      32
#define ROWBLKS (N_NODES / BM)      // 128
#define GEMM_BLOCKS (ROWBLKS * KSPLIT)  // 1024
#define CSR_BLOCKS  1024

typedef unsigned long long ull;

// ---------------- packed f32x2 helpers (Blackwell) ----------------
__device__ __forceinline__ ull pack2(float a) {
    ull r;
    asm("mov.b64 %0, {%1, %1};" : "=l"(r) : "f"(a));
    return r;
}
__device__ __forceinline__ void fma2(ull& d, ull a, ull b) {
    asm("fma.rn.f32x2 %0, %1, %2, %0;" : "+l"(d) : "l"(a), "l"(b));
}
__device__ __forceinline__ void add2(ull& d, ull a) {
    asm("add.rn.f32x2 %0, %0, %1;" : "+l"(d) : "l"(a));
}
__device__ __forceinline__ void unpack2(ull v, float& lo, float& hi) {
    asm("mov.b64 {%0, %1}, %2;" : "=f"(lo), "=f"(hi) : "l"(v));
}

// ---------------- scratch ----------------
__device__ float g_x [N_NODES * D_H];
__device__ float g_el[N_NODES * HEADS];
__device__ float g_er[N_NODES * HEADS];
__device__ float g_h1[N_NODES * D_H * HEADS];
__device__ float g_h2[N_NODES * D_H * HEADS];
__device__ float g_part[KSPLIT * N_NODES * D_H];
__device__ int   g_cols[N_NODES * MAXD];
__device__ int   g_deg [N_NODES];
__device__ unsigned g_cnt[ROWBLKS];   // split-K completion counters (self-resetting)

// ---- fused: split-K GEMM + last-block reduce + el/er proj (+ CSR blocks) --
// gemm blocks [0, GEMM_BLOCKS): rowblock = bx>>3 (32 rows), split = bx&7 (K=64).
// csr blocks  [GEMM_BLOCKS, ...): 4 warps, warp per adjacency row (layer 0 only).
__global__ __launch_bounds__(128) void gemm_fused_kernel(const float* __restrict__ adj,
                                                         const float* __restrict__ A,
                                                         const float* __restrict__ B,
                                                         const float* __restrict__ al,
                                                         const float* __restrict__ ar,
                                                         float* __restrict__ X, int H) {
    if (blockIdx.x >= GEMM_BLOCKS) {
        // ---------------- CSR build ----------------
        int warp = (blockIdx.x - GEMM_BLOCKS) * 4 + (threadIdx.x >> 5);
        int lane = threadIdx.x & 31;
        const float4* a = reinterpret_cast<const float4*>(adj + (size_t)warp * N_NODES);
        int* outc = g_cols + warp * MAXD;
        int base = 0;
        for (int j0 = 0; j0 < N_NODES; j0 += 128) {
            float4 v = a[(j0 >> 2) + lane];
            float vv[4] = {v.x, v.y, v.z, v.w};
            #pragma unroll
            for (int c = 0; c < 4; c++) {
                unsigned m = __ballot_sync(0xffffffffu, vv[c] != 0.0f);
                if (vv[c] != 0.0f) {
                    int pos = base + __popc(m & ((1u << lane) - 1u));
                    if (pos < MAXD) outc[pos] = j0 + lane * 4 + c;
                }
                base += __popc(m);
            }
        }
        if (lane == 0) g_deg[warp] = base < MAXD ? base : MAXD;
        return;
    }

    // ------- GEMM partial: 32 rows x 64 cols, K slice 64, 4x4 micro-tile ---
    __shared__ float AsT[KS][36];      // [k][row], row XOR-swizzled in groups of 4
    __shared__ float sProj[1024];      // al/ar staging for the reduce epilogue
    __shared__ int   s_last;

    int tid = threadIdx.x;
    int tx = tid & 15, ty = tid >> 4;
    int rb      = blockIdx.x >> 3;
    int split   = blockIdx.x & 7;
    int rowBase = rb * BM;
    int k0      = split * KS;

    // stage whole A slice [32 rows x 64 k], transposed + swizzled. 4 float4/thread.
    #pragma unroll
    for (int s = 0; s < 4; s++) {
        int idx = tid + 128 * s;
        int row = idx >> 4;               // 0..31
        int kk  = (idx & 15) << 2;        // 0..60
        float4 v = *reinterpret_cast<const float4*>(
            A + (size_t)(rowBase + row) * KDIM + k0 + kk);
        float av[4] = {v.x, v.y, v.z, v.w};
        #pragma unroll
        for (int i = 0; i < 4; i++) {
            int k = kk + i;
            AsT[k][row ^ (((k >> 3) & 3) << 2)] = av[i];
        }
    }
    __syncthreads();

    ull acc[4][2] = {{0,0},{0,0},{0,0},{0,0}};
    const float* Bb = B + (size_t)k0 * 64 + tx * 4;

    #pragma unroll 16
    for (int k = 0; k < KS; k++) {
        float4 av = *reinterpret_cast<const float4*>(&AsT[k][(ty ^ ((k >> 3) & 3)) << 2]);
        ulonglong2 bb = *reinterpret_cast<const ulonglong2*>(Bb + (size_t)k * 64);
        ull pa0 = pack2(av.x), pa1 = pack2(av.y), pa2 = pack2(av.z), pa3 = pack2(av.w);
        fma2(acc[0][0], pa0, bb.x); fma2(acc[0][1], pa0, bb.y);
        fma2(acc[1][0], pa1, bb.x); fma2(acc[1][1], pa1, bb.y);
        fma2(acc[2][0], pa2, bb.x); fma2(acc[2][1], pa2, bb.y);
        fma2(acc[3][0], pa3, bb.x); fma2(acc[3][1], pa3, bb.y);
    }

    float* P = g_part + (size_t)split * (N_NODES * D_H);
    #pragma unroll
    for (int i = 0; i < 4; i++) {
        int r = rowBase + ty * 4 + i;
        ulonglong2 v; v.x = acc[i][0]; v.y = acc[i][1];
        *reinterpret_cast<ulonglong2*>(P + (size_t)r * 64 + tx * 4) = v;
    }

    // ---- last-block-done: reduce 8 partials (fixed order) + projection ----
    __syncthreads();
    if (tid == 0) {
        __threadfence();
        unsigned old = atomicAdd(&g_cnt[rb], 1u);
        int last = (old == KSPLIT - 1);
        if (last) { g_cnt[rb] = 0; __threadfence(); }
        s_last = last;
    }
    __syncthreads();
    if (!s_last) return;

    float* sC = &AsT[0][0];   // reuse: 32*64 = 2048 floats <= 64*36
    const size_t SZ = (size_t)N_NODES * D_H;
    #pragma unroll
    for (int s = 0; s < 4; s++) {
        int e4 = tid + 128 * s;                      // float4 index within tile
        size_t off = (size_t)rowBase * 64 + (size_t)e4 * 4;
        const float4* p = reinterpret_cast<const float4*>(g_part + off);
        float4 v0 = p[0];
        float4 v1 = p[SZ/4],   v2 = p[2*SZ/4], v3 = p[3*SZ/4];
        float4 v4 = p[4*SZ/4], v5 = p[5*SZ/4], v6 = p[6*SZ/4], v7 = p[7*SZ/4];
        float4 r01, r23, r45, r67, ra, rb4, rr;
        r01.x=v0.x+v1.x; r01.y=v0.y+v1.y; r01.z=v0.z+v1.z; r01.w=v0.w+v1.w;
        r23.x=v2.x+v3.x; r23.y=v2.y+v3.y; r23.z=v2.z+v3.z; r23.w=v2.w+v3.w;
        r45.x=v4.x+v5.x; r45.y=v4.y+v5.y; r45.z=v4.z+v5.z; r45.w=v4.w+v5.w;
        r67.x=v6.x+v7.x; r67.y=v6.y+v7.y; r67.z=v6.z+v7.z; r67.w=v6.w+v7.w;
        ra.x=r01.x+r23.x; ra.y=r01.y+r23.y; ra.z=r01.z+r23.z; ra.w=r01.w+r23.w;
        rb4.x=r45.x+r67.x; rb4.y=r45.y+r67.y; rb4.z=r45.z+r67.z; rb4.w=r45.w+r67.w;
        rr.x=ra.x+rb4.x; rr.y=ra.y+rb4.y; rr.z=ra.z+rb4.z; rr.w=ra.w+rb4.w;
        *reinterpret_cast<float4*>(X + off) = rr;
        *reinterpret_cast<float4*>(sC + e4 * 4) = rr;
    }
    for (int idx = tid; idx < 64 * H; idx += 128) {
        sProj[idx]       = al[idx];
        sProj[512 + idx] = ar[idx];
    }
    __syncthreads();
    for (int t = tid; t < 32 * H; t += 128) {
        int r = t / H, h = t - r * H;
        float sl = 0.f, sr = 0.f;
        #pragma unroll
        for (int d = 0; d < 64; d++) {
            float cv = sC[r * 64 + d];
            sl += cv * sProj[d * H + h];
            sr += cv * sProj[512 + d * H + h];
        }
        g_el[(rowBase + r) * H + h] = sl;
        g_er[(rowBase + r) * H + h] = sr;
    }
}

// ---------------- 8-head aggregation: block per node, 128 threads ----------
__global__ __launch_bounds__(128) void agg8_kernel(const float* __restrict__ bias,
                                                   float* __restrict__ out, int act) {
    int i   = blockIdx.x;
    int tid = threadIdx.x;
    int h   = tid >> 4;
    int q   = tid & 15;

    __shared__ int   s_cols[CH];
    __shared__ float s_el[HEADS];
    __shared__ ull   s_w[HEADS][CH];

    if (tid < HEADS) s_el[tid] = g_el[i * HEADS + tid];
    int deg = g_deg[i];
    const int* cols = g_cols + (size_t)i * MAXD;
    const float* xq = g_x + q * 4;

    ull acc0 = 0ull, acc1 = 0ull, sw2 = 0ull;

    for (int j0 = 0; j0 < deg; j0 += CH) {
        int cl = min(CH, deg - j0);
        if (tid < cl) s_cols[tid] = cols[j0 + tid];
        __syncthreads();
        for (int idx = tid; idx < cl * HEADS; idx += 128) {
            int jj = idx >> 3, hh = idx & 7;
            float s = s_el[hh] + g_er[s_cols[jj] * HEADS + hh];
            s = (s >= 0.f) ? s : 0.2f * s;
            s_w[hh][jj] = pack2(__expf(s));
        }
        __syncthreads();
        #pragma unroll 8
        for (int jj = 0; jj < cl; jj++) {
            ull pw = s_w[h][jj];
            ulonglong2 xv = *reinterpret_cast<const ulonglong2*>(xq + (size_t)s_cols[jj] * D_H);
            fma2(acc0, pw, xv.x);
            fma2(acc1, pw, xv.y);
            add2(sw2, pw);
        }
        __syncthreads();
    }

    float sw, dmy;
    unpack2(sw2, sw, dmy);
    float inv = 1.0f / fmaxf(sw, 1e-12f);
    float4 bv = *reinterpret_cast<const float4*>(bias + q * 4);
    float v0, v1, v2, v3;
    unpack2(acc0, v0, v1);
    unpack2(acc1, v2, v3);
    v0 = v0 * inv + bv.x; v1 = v1 * inv + bv.y;
    v2 = v2 * inv + bv.z; v3 = v3 * inv + bv.w;
    if (act) {
        v0 = (v0 > 0.f) ? v0 : expm1f(v0);
        v1 = (v1 > 0.f) ? v1 : expm1f(v1);
        v2 = (v2 > 0.f) ? v2 : expm1f(v2);
        v3 = (v3 > 0.f) ? v3 : expm1f(v3);
    }
    float4 ov = make_float4(v0, v1, v2, v3);
    *reinterpret_cast<float4*>(out + (size_t)i * (HEADS * D_H) + h * D_H + q * 4) = ov;
}

// ---------------- 1-head aggregation: block per node, 64 threads -----------
__global__ __launch_bounds__(64) void agg1_kernel(const float* __restrict__ bias,
                                                  float* __restrict__ out) {
    int i   = blockIdx.x;
    int tid = threadIdx.x;   // = d

    __shared__ int   s_cols[CH];
    __shared__ float s_w[CH];

    float eli = g_el[i];
    int deg = g_deg[i];
    const int* cols = g_cols + (size_t)i * MAXD;
    float acc = 0.f, sw = 0.f;

    for (int j0 = 0; j0 < deg; j0 += CH) {
        int cl = min(CH, deg - j0);
        if (tid < cl) {
            int c = cols[j0 + tid];
            s_cols[tid] = c;
            float s = eli + g_er[c];
            s = (s >= 0.f) ? s : 0.2f * s;
            s_w[tid] = __expf(s);
        }
        __syncthreads();
        #pragma unroll 8
        for (int jj = 0; jj < cl; jj++) {
            float wv = s_w[jj];
            acc += wv * g_x[(size_t)s_cols[jj] * D_H + tid];
            sw  += wv;
        }
        __syncthreads();
    }

    float v = acc / fmaxf(sw, 1e-12f) + bias[tid];
    out[(size_t)i * D_H + tid] = v;
}

// ---------------- launch ---------------------------------------------------
extern "C" void kernel_launch(void* const* d_in, const int* in_sizes, int n_in,
                              void* d_out, int out_size) {
    const float* adj  = (const float*)d_in[0];
    const float* feat = (const float*)d_in[1];
    const float* W0   = (const float*)d_in[2];
    const float* al0  = (const float*)d_in[3];
    const float* ar0  = (const float*)d_in[4];
    const float* b0   = (const float*)d_in[5];
    const float* W1   = (const float*)d_in[6];
    const float* al1  = (const float*)d_in[7];
    const float* ar1  = (const float*)d_in[8];
    const float* b1   = (const float*)d_in[9];
    const float* W2   = (const float*)d_in[10];
    const float* al2  = (const float*)d_in[11];
    const float* ar2  = (const float*)d_in[12];
    const float* b2   = (const float*)d_in[13];
    float* out = (float*)d_out;

    float *x, *h1, *h2;
    cudaGetSymbolAddress((void**)&x,  g_x);
    cudaGetSymbolAddress((void**)&h1, g_h1);
    cudaGetSymbolAddress((void**)&h2, g_h2);

    // layer 0 (CSR build fused into the GEMM launch as extra blocks)
    gemm_fused_kernel<<<GEMM_BLOCKS + CSR_BLOCKS, 128>>>(adj, feat, W0, al0, ar0, x, HEADS);
    agg8_kernel<<<N_NODES, 128>>>(b0, h1, 1);

    // layer 1
    gemm_fused_kernel<<<GEMM_BLOCKS, 128>>>(adj, h1, W1, al1, ar1, x, HEADS);
    agg8_kernel<<<N_NODES, 128>>>(b1, h2, 1);

    // layer 2
    gemm_fused_kernel<<<GEMM_BLOCKS, 128>>>(adj, h2, W2, al2, ar2, x, 1);
    agg1_kernel<<<N_NODES, 64>>>(b2, out);
}

// round 9
// speedup vs baseline: 1.2974x; 1.2974x over previous
#include <cuda_runtime.h>
#include <math.h>

#define N_NODES 4096
#define KDIM    512
#define D_H     64
#define HEADS   8
#define MAXD    192
#define CH      64
#define KSPLIT  8
#define KS      64
#define BM      32
#define ROWBLKS (N_NODES / BM)
#define GEMM_BLOCKS (ROWBLKS * KSPLIT)  // 1024
#define CSR_BLOCKS  1024

typedef unsigned long long ull;

// ---------------- packed f32x2 helpers (Blackwell) ----------------
__device__ __forceinline__ ull pack2(float a) {
    ull r;
    asm("mov.b64 %0, {%1, %1};" : "=l"(r) : "f"(a));
    return r;
}
__device__ __forceinline__ void fma2(ull& d, ull a, ull b) {
    asm("fma.rn.f32x2 %0, %1, %2, %0;" : "+l"(d) : "l"(a), "l"(b));
}
__device__ __forceinline__ void add2(ull& d, ull a) {
    asm("add.rn.f32x2 %0, %0, %1;" : "+l"(d) : "l"(a));
}
__device__ __forceinline__ void unpack2(ull v, float& lo, float& hi) {
    asm("mov.b64 {%0, %1}, %2;" : "=f"(lo), "=f"(hi) : "l"(v));
}

// ---------------- scratch ----------------
__device__ float g_x [N_NODES * D_H];
__device__ float g_el[N_NODES * HEADS];
__device__ float g_er[N_NODES * HEADS];
__device__ float g_h1[N_NODES * D_H * HEADS];
__device__ float g_h2[N_NODES * D_H * HEADS];
__device__ float g_part[KSPLIT * N_NODES * D_H];
__device__ int   g_cols[N_NODES * MAXD];
__device__ int   g_deg [N_NODES];

// ---- split-K GEMM (+ fused CSR build in extra blocks) — round-7 version ---
__global__ __launch_bounds__(128) void gemm_csr_kernel(const float* __restrict__ adj,
                                                       const float* __restrict__ A,
                                                       const float* __restrict__ B) {
    if (blockIdx.x >= GEMM_BLOCKS) {
        int warp = (blockIdx.x - GEMM_BLOCKS) * 4 + (threadIdx.x >> 5);
        int lane = threadIdx.x & 31;
        const float4* a = reinterpret_cast<const float4*>(adj + (size_t)warp * N_NODES);
        int* outc = g_cols + warp * MAXD;
        int base = 0;
        for (int j0 = 0; j0 < N_NODES; j0 += 128) {
            float4 v = a[(j0 >> 2) + lane];
            float vv[4] = {v.x, v.y, v.z, v.w};
            #pragma unroll
            for (int c = 0; c < 4; c++) {
                unsigned m = __ballot_sync(0xffffffffu, vv[c] != 0.0f);
                if (vv[c] != 0.0f) {
                    int pos = base + __popc(m & ((1u << lane) - 1u));
                    if (pos < MAXD) outc[pos] = j0 + lane * 4 + c;
                }
                base += __popc(m);
            }
        }
        if (lane == 0) g_deg[warp] = base < MAXD ? base : MAXD;
        return;
    }

    __shared__ float AsT[32][36];
    __shared__ float Bs[32][64];
    int tid = threadIdx.x;
    int tx = tid & 15, ty = tid >> 4;
    int rowBase = (blockIdx.x >> 3) * BM;
    int k0      = (blockIdx.x & 7) * KS;

    float4 a_n[2], b_n[4];
    #pragma unroll
    for (int s = 0; s < 2; s++) {
        int idx = tid + 128 * s;
        a_n[s] = *reinterpret_cast<const float4*>(
            A + (size_t)(rowBase + (idx >> 3)) * KDIM + k0 + ((idx & 7) << 2));
    }
    #pragma unroll
    for (int s = 0; s < 4; s++) {
        int idx = tid + 128 * s;
        b_n[s] = *reinterpret_cast<const float4*>(
            B + (size_t)(k0 + (idx >> 4)) * 64 + ((idx & 15) << 2));
    }

    ull acc[4][2] = {{0,0},{0,0},{0,0},{0,0}};

    for (int kt = 0; kt < KS; kt += 32) {
        #pragma unroll
        for (int s = 0; s < 2; s++) {
            int idx = tid + 128 * s;
            int row = idx >> 3;
            int kk  = (idx & 7) << 2;
            float av[4] = {a_n[s].x, a_n[s].y, a_n[s].z, a_n[s].w};
            #pragma unroll
            for (int i = 0; i < 4; i++) {
                int k = kk + i;
                AsT[k][row ^ (((k >> 3) & 3) << 2)] = av[i];
            }
        }
        #pragma unroll
        for (int s = 0; s < 4; s++) {
            int idx = tid + 128 * s;
            *reinterpret_cast<float4*>(&Bs[idx >> 4][(idx & 15) << 2]) = b_n[s];
        }
        __syncthreads();
        if (kt + 32 < KS) {
            #pragma unroll
            for (int s = 0; s < 2; s++) {
                int idx = tid + 128 * s;
                a_n[s] = *reinterpret_cast<const float4*>(
                    A + (size_t)(rowBase + (idx >> 3)) * KDIM + k0 + kt + 32 + ((idx & 7) << 2));
            }
            #pragma unroll
            for (int s = 0; s < 4; s++) {
                int idx = tid + 128 * s;
                b_n[s] = *reinterpret_cast<const float4*>(
                    B + (size_t)(k0 + kt + 32 + (idx >> 4)) * 64 + ((idx & 15) << 2));
            }
        }
        #pragma unroll
        for (int k = 0; k < 32; k++) {
            int sr = (ty ^ ((k >> 3) & 3)) << 2;
            float4 av = *reinterpret_cast<const float4*>(&AsT[k][sr]);
            ulonglong2 bb = *reinterpret_cast<const ulonglong2*>(&Bs[k][tx * 4]);
            ull pa0 = pack2(av.x), pa1 = pack2(av.y), pa2 = pack2(av.z), pa3 = pack2(av.w);
            fma2(acc[0][0], pa0, bb.x); fma2(acc[0][1], pa0, bb.y);
            fma2(acc[1][0], pa1, bb.x); fma2(acc[1][1], pa1, bb.y);
            fma2(acc[2][0], pa2, bb.x); fma2(acc[2][1], pa2, bb.y);
            fma2(acc[3][0], pa3, bb.x); fma2(acc[3][1], pa3, bb.y);
        }
        __syncthreads();
    }

    float* P = g_part + (size_t)(blockIdx.x & 7) * (N_NODES * D_H);
    #pragma unroll
    for (int i = 0; i < 4; i++) {
        int r = rowBase + ty * 4 + i;
        ulonglong2 v; v.x = acc[i][0]; v.y = acc[i][1];
        *reinterpret_cast<ulonglong2*>(P + (size_t)r * 64 + tx * 4) = v;
    }
}

// ---- reduce 8 split-K partials (fixed order) + el/er projection ----------
__global__ __launch_bounds__(256) void reduce_proj_kernel(const float* __restrict__ al,
                                                          const float* __restrict__ ar,
                                                          float* __restrict__ X, int H) {
    __shared__ float sC[4][64];
    __shared__ float sAl[512];
    __shared__ float sAr[512];
    int tid = threadIdx.x;
    int r = tid >> 6, d = tid & 63;
    int row = blockIdx.x * 4 + r;
    size_t off = (size_t)row * 64 + d;
    const size_t SZ = (size_t)N_NODES * D_H;
    float p0 = g_part[off]          + g_part[SZ + off];
    float p1 = g_part[2*SZ + off]   + g_part[3*SZ + off];
    float p2 = g_part[4*SZ + off]   + g_part[5*SZ + off];
    float p3 = g_part[6*SZ + off]   + g_part[7*SZ + off];
    float v = (p0 + p1) + (p2 + p3);
    X[off] = v;
    sC[r][d] = v;
    for (int idx = tid; idx < 64 * H; idx += 256) {
        sAl[idx] = al[idx];
        sAr[idx] = ar[idx];
    }
    __syncthreads();
    if (tid < 4 * H) {
        int rr = (H == 8) ? (tid >> 3) : tid;
        int h  = (H == 8) ? (tid & 7)  : 0;
        float sl = 0.f, sr = 0.f;
        #pragma unroll
        for (int dd = 0; dd < 64; dd++) {
            float cv = sC[rr][dd];
            sl += cv * sAl[dd * H + h];
            sr += cv * sAr[dd * H + h];
        }
        g_el[(blockIdx.x * 4 + rr) * H + h] = sl;
        g_er[(blockIdx.x * 4 + rr) * H + h] = sr;
    }
}

// ---------------- 8-head aggregation: WARP per node, 4 nodes/block ---------
// lane = (qg, h): h = lane&7, qg = lane>>3. Lane owns d = qg*16 .. qg*16+15
// for head h. No __syncthreads — warps are independent.
__global__ __launch_bounds__(128) void agg8_kernel(const float* __restrict__ bias,
                                                   float* __restrict__ out, int act) {
    int w    = threadIdx.x >> 5;
    int lane = threadIdx.x & 31;
    int i    = blockIdx.x * 4 + w;
    int h    = lane & 7;
    int qg   = lane >> 3;

    __shared__ int s_cols[4][CH];
    __shared__ ull s_w[4][CH][HEADS];   // 16 KB

    int deg = g_deg[i];
    const int* cols = g_cols + (size_t)i * MAXD;
    float elh = g_el[i * HEADS + h];
    const float* xbase = g_x + qg * 16;

    ull acc[8] = {0,0,0,0,0,0,0,0};
    ull sw2 = 0ull;

    for (int j0 = 0; j0 < deg; j0 += CH) {
        int cl = min(CH, deg - j0);
        if (lane < cl)      s_cols[w][lane]      = cols[j0 + lane];
        if (lane + 32 < cl) s_cols[w][lane + 32] = cols[j0 + lane + 32];
        __syncwarp();
        // weights: idx = it*32 + lane -> jj = idx>>3, head = idx&7 == lane&7 == h
        for (int idx = lane; idx < cl * 8; idx += 32) {
            int jj = idx >> 3;
            float s = elh + g_er[s_cols[w][jj] * HEADS + h];
            s = (s >= 0.f) ? s : 0.2f * s;
            s_w[w][jj][h] = pack2(__expf(s));
        }
        __syncwarp();
        #pragma unroll 2
        for (int jj = 0; jj < cl; jj++) {
            ull pw = s_w[w][jj][h];
            const float* xr = xbase + (size_t)s_cols[w][jj] * D_H;
            ulonglong2 x0 = *reinterpret_cast<const ulonglong2*>(xr);
            ulonglong2 x1 = *reinterpret_cast<const ulonglong2*>(xr + 4);
            ulonglong2 x2 = *reinterpret_cast<const ulonglong2*>(xr + 8);
            ulonglong2 x3 = *reinterpret_cast<const ulonglong2*>(xr + 12);
            fma2(acc[0], pw, x0.x); fma2(acc[1], pw, x0.y);
            fma2(acc[2], pw, x1.x); fma2(acc[3], pw, x1.y);
            fma2(acc[4], pw, x2.x); fma2(acc[5], pw, x2.y);
            fma2(acc[6], pw, x3.x); fma2(acc[7], pw, x3.y);
            add2(sw2, pw);
        }
        __syncwarp();
    }

    float sw, dmy;
    unpack2(sw2, sw, dmy);
    float inv = 1.0f / fmaxf(sw, 1e-12f);
    float* o = out + (size_t)i * (HEADS * D_H) + h * D_H + qg * 16;
    const float* bq = bias + qg * 16;
    #pragma unroll
    for (int t4 = 0; t4 < 4; t4++) {
        float v0, v1, v2, v3;
        unpack2(acc[t4*2],   v0, v1);
        unpack2(acc[t4*2+1], v2, v3);
        v0 = v0 * inv + bq[t4*4+0];
        v1 = v1 * inv + bq[t4*4+1];
        v2 = v2 * inv + bq[t4*4+2];
        v3 = v3 * inv + bq[t4*4+3];
        if (act) {
            v0 = (v0 > 0.f) ? v0 : expm1f(v0);
            v1 = (v1 > 0.f) ? v1 : expm1f(v1);
            v2 = (v2 > 0.f) ? v2 : expm1f(v2);
            v3 = (v3 > 0.f) ? v3 : expm1f(v3);
        }
        float4 ov = make_float4(v0, v1, v2, v3);
        *reinterpret_cast<float4*>(o + t4 * 4) = ov;
    }
}

// ---------------- 1-head aggregation: WARP per node, 4 nodes/block ---------
// lane owns d = lane*2, lane*2+1.
__global__ __launch_bounds__(128) void agg1_kernel(const float* __restrict__ bias,
                                                   float* __restrict__ out) {
    int w    = threadIdx.x >> 5;
    int lane = threadIdx.x & 31;
    int i    = blockIdx.x * 4 + w;

    __shared__ int s_cols[4][CH];
    __shared__ ull s_w[4][CH];

    int deg = g_deg[i];
    const int* cols = g_cols + (size_t)i * MAXD;
    float eli = g_el[i];
    const float* xbase = g_x + lane * 2;

    ull acc = 0ull, sw2 = 0ull;

    for (int j0 = 0; j0 < deg; j0 += CH) {
        int cl = min(CH, deg - j0);
        if (lane < cl) {
            int c = cols[j0 + lane];
            s_cols[w][lane] = c;
            float s = eli + g_er[c];
            s = (s >= 0.f) ? s : 0.2f * s;
            s_w[w][lane] = pack2(__expf(s));
        }
        if (lane + 32 < cl) {
            int c = cols[j0 + lane + 32];
            s_cols[w][lane + 32] = c;
            float s = eli + g_er[c];
            s = (s >= 0.f) ? s : 0.2f * s;
            s_w[w][lane + 32] = pack2(__expf(s));
        }
        __syncwarp();
        #pragma unroll 4
        for (int jj = 0; jj < cl; jj++) {
            ull pw = s_w[w][jj];
            ull xv = *reinterpret_cast<const ull*>(xbase + (size_t)s_cols[w][jj] * D_H);
            fma2(acc, pw, xv);
            add2(sw2, pw);
        }
        __syncwarp();
    }

    float sw, dmy;
    unpack2(sw2, sw, dmy);
    float inv = 1.0f / fmaxf(sw, 1e-12f);
    float v0, v1;
    unpack2(acc, v0, v1);
    v0 = v0 * inv + bias[lane * 2];
    v1 = v1 * inv + bias[lane * 2 + 1];
    float2 ov = make_float2(v0, v1);
    *reinterpret_cast<float2*>(out + (size_t)i * D_H + lane * 2) = ov;
}

// ---------------- launch ---------------------------------------------------
extern "C" void kernel_launch(void* const* d_in, const int* in_sizes, int n_in,
                              void* d_out, int out_size) {
    const float* adj  = (const float*)d_in[0];
    const float* feat = (const float*)d_in[1];
    const float* W0   = (const float*)d_in[2];
    const float* al0  = (const float*)d_in[3];
    const float* ar0  = (const float*)d_in[4];
    const float* b0   = (const float*)d_in[5];
    const float* W1   = (const float*)d_in[6];
    const float* al1  = (const float*)d_in[7];
    const float* ar1  = (const float*)d_in[8];
    const float* b1   = (const float*)d_in[9];
    const float* W2   = (const float*)d_in[10];
    const float* al2  = (const float*)d_in[11];
    const float* ar2  = (const float*)d_in[12];
    const float* b2   = (const float*)d_in[13];
    float* out = (float*)d_out;

    float *x, *h1, *h2;
    cudaGetSymbolAddress((void**)&x,  g_x);
    cudaGetSymbolAddress((void**)&h1, g_h1);
    cudaGetSymbolAddress((void**)&h2, g_h2);

    // layer 0 (CSR build fused into the GEMM launch as extra blocks)
    gemm_csr_kernel<<<GEMM_BLOCKS + CSR_BLOCKS, 128>>>(adj, feat, W0);
    reduce_proj_kernel<<<N_NODES / 4, 256>>>(al0, ar0, x, HEADS);
    agg8_kernel<<<N_NODES / 4, 128>>>(b0, h1, 1);

    // layer 1
    gemm_csr_kernel<<<GEMM_BLOCKS, 128>>>(adj, h1, W1);
    reduce_proj_kernel<<<N_NODES / 4, 256>>>(al1, ar1, x, HEADS);
    agg8_kernel<<<N_NODES / 4, 128>>>(b1, h2, 1);

    // layer 2
    gemm_csr_kernel<<<GEMM_BLOCKS, 128>>>(adj, h2, W2);
    reduce_proj_kernel<<<N_NODES / 4, 256>>>(al2, ar2, x, 1);
    agg1_kernel<<<N_NODES / 4, 128>>>(b2, out);
}